// round 16
// baseline (speedup 1.0000x reference)
#include <cuda_runtime.h>
#include <math_constants.h>

#define BB 512
#define SS 200
#define UU 50
#define DD 32
#define NITER 13          // ceil(50 rows / 4 rows-per-iter)
#define SMROWS 52         // padded rows in the smem tile

__global__ __launch_bounds__(128, 6)   // cap 85 regs, 6 blocks -> 24 warps/SM
void DIB_attn_kernel(const float* __restrict__ cur_user,   // [B, D]
                     const float* __restrict__ sim_user,   // [B, S, U, D]
                     const float* __restrict__ cur_item,   // [B, S, D]
                     const int* __restrict__ mask,          // [B, S, U] (bool -> int32)
                     float* __restrict__ out)               // [B, S, D]
{
    __shared__ float4 sm[4][SMROWS * 8];   // 4 warps * 6656B = 26624B static

    const unsigned FULL = 0xffffffffu;
    int w    = threadIdx.x >> 5;
    int lane = threadIdx.x & 31;
    int sub  = lane >> 3;       // 0..3 : row within 4-row group
    int quad = lane & 7;        // 0..7 : dims quad*4 .. quad*4+3

    int b = blockIdx.y;
    int spair   = blockIdx.x * 4 + w;            // 0..99
    int tileA_id = b * SS + spair * 2;           // tiles share b -> shared cu
    int tileB_id = tileA_id + 1;

    // ---- Both masks up front: ONE round-trip covers both tiles ----
    const int* mrA = mask + (long long)tileA_id * UU;
    const int* mrB = mask + (long long)tileB_id * UU;
    int a0 = __ldg(mrA + lane);
    int b0 = __ldg(mrB + lane);
    int a1 = (lane + 32 < UU) ? __ldg(mrA + 32 + lane) : 1;
    int b1 = (lane + 32 < UU) ? __ldg(mrB + 32 + lane) : 1;

    float4 cu = __ldg((const float4*)(cur_user + b * DD) + quad);

    unsigned bitsA0 = __ballot_sync(FULL, a0 == 0);
    unsigned bitsA1 = __ballot_sync(FULL, (lane + 32 < UU) && (a1 == 0));
    unsigned bitsB0 = __ballot_sync(FULL, b0 == 0);
    unsigned bitsB1 = __ballot_sync(FULL, (lane + 32 < UU) && (b1 == 0));

    bool degA = (bitsA0 | bitsA1) == 0u;   // all masked -> uniform 1/50 over
    bool degB = (bitsB0 | bitsB1) == 0u;   //   fully-loaded tile = reference
    if (degA) { bitsA0 = 0xffffffffu; bitsA1 = 0x3ffffu; }
    if (degB) { bitsB0 = 0xffffffffu; bitsB1 = 0x3ffffu; }

    const float* tA = sim_user + (long long)tileA_id * (UU * DD);
    const float* tB = sim_user + (long long)tileB_id * (UU * DD);

    // ---- Burst A: 13 predicated LDG.128 into registers ----
    float4 v[NITER];
    #pragma unroll
    for (int i = 0; i < NITER; i++) {
        int u = i * 4 + sub;
        bool un = (u < UU) &&
            (((u < 32 ? (bitsA0 >> u) : (bitsA1 >> (u - 32))) & 1u) != 0u);
        float4 vv = make_float4(0.f, 0.f, 0.f, 0.f);
        if (un) vv = __ldg((const float4*)(tA + u * DD) + quad);
        v[i] = vv;
    }

    // ---- Burst B: 13 predicated cp.async into smem (no reg payload).
    //      "memory" clobbers pin burst A before these and compute after. ----
    #pragma unroll
    for (int i = 0; i < NITER; i++) {
        int u = i * 4 + sub;
        bool un = (u < UU) &&
            (((u < 32 ? (bitsB0 >> u) : (bitsB1 >> (u - 32))) & 1u) != 0u);
        if (un) {
            unsigned sa = (unsigned)__cvta_generic_to_shared(&sm[w][u * 8 + quad]);
            const float* ga = tB + u * DD + quad * 4;
            asm volatile("cp.async.cg.shared.global [%0], [%1], 16;\n"
                         :: "r"(sa), "l"(ga) : "memory");
        }
    }
    asm volatile("cp.async.commit_group;\n" ::: "memory");

    // ---- Compute A (lean no-max softmax, validated R11-R13) while B streams ----
    {
        float  s   = 0.0f;
        float4 acc = make_float4(0.f, 0.f, 0.f, 0.f);
        #pragma unroll
        for (int i = 0; i < NITER; i++) {
            int u = i * 4 + sub;
            bool un = (u < UU) &&
                (((u < 32 ? (bitsA0 >> u) : (bitsA1 >> (u - 32))) & 1u) != 0u);
            float p = v[i].x * cu.x + v[i].y * cu.y + v[i].z * cu.z + v[i].w * cu.w;
            p += __shfl_xor_sync(FULL, p, 1);
            p += __shfl_xor_sync(FULL, p, 2);
            p += __shfl_xor_sync(FULL, p, 4);
            float e = un ? (degA ? 1.0f : __expf(p)) : 0.0f;
            s += e;
            acc.x = fmaf(e, v[i].x, acc.x);   // v=0 for unloaded rows
            acc.y = fmaf(e, v[i].y, acc.y);
            acc.z = fmaf(e, v[i].z, acc.z);
            acc.w = fmaf(e, v[i].w, acc.w);
        }
        s += __shfl_xor_sync(FULL, s, 8);
        s += __shfl_xor_sync(FULL, s, 16);
        float inv = __frcp_rn(s);
        float4 o = make_float4(acc.x * inv, acc.y * inv, acc.z * inv, acc.w * inv);
        #pragma unroll
        for (int off = 8; off <= 16; off <<= 1) {
            o.x += __shfl_xor_sync(FULL, o.x, off);
            o.y += __shfl_xor_sync(FULL, o.y, off);
            o.z += __shfl_xor_sync(FULL, o.z, off);
            o.w += __shfl_xor_sync(FULL, o.w, off);
        }
        if (sub == 0) {
            float4 ci = __ldg((const float4*)(cur_item + (long long)tileA_id * DD) + quad);
            ((float4*)(out + (long long)tileA_id * DD))[quad] =
                make_float4(o.x + ci.x, o.y + ci.y, o.z + ci.z, o.w + ci.w);
        }
    }

    // ---- Compute B from smem ----
    asm volatile("cp.async.wait_group 0;\n" ::: "memory");
    __syncwarp();
    {
        float  s   = 0.0f;
        float4 acc = make_float4(0.f, 0.f, 0.f, 0.f);
        #pragma unroll
        for (int i = 0; i < NITER; i++) {
            int u = i * 4 + sub;
            bool un = (u < UU) &&
                (((u < 32 ? (bitsB0 >> u) : (bitsB1 >> (u - 32))) & 1u) != 0u);
            // always read (u <= 51 < SMROWS, in-bounds); garbage for masked
            // rows is selected away (never enters arithmetic when e == 0)
            float4 vv = sm[w][u * 8 + quad];
            float p = vv.x * cu.x + vv.y * cu.y + vv.z * cu.z + vv.w * cu.w;
            p += __shfl_xor_sync(FULL, p, 1);
            p += __shfl_xor_sync(FULL, p, 2);
            p += __shfl_xor_sync(FULL, p, 4);
            float e = un ? (degB ? 1.0f : __expf(p)) : 0.0f;
            s += e;
            if (e != 0.0f) {                  // guard: never touch garbage vv
                acc.x = fmaf(e, vv.x, acc.x);
                acc.y = fmaf(e, vv.y, acc.y);
                acc.z = fmaf(e, vv.z, acc.z);
                acc.w = fmaf(e, vv.w, acc.w);
            }
        }
        s += __shfl_xor_sync(FULL, s, 8);
        s += __shfl_xor_sync(FULL, s, 16);
        float inv = __frcp_rn(s);
        float4 o = make_float4(acc.x * inv, acc.y * inv, acc.z * inv, acc.w * inv);
        #pragma unroll
        for (int off = 8; off <= 16; off <<= 1) {
            o.x += __shfl_xor_sync(FULL, o.x, off);
            o.y += __shfl_xor_sync(FULL, o.y, off);
            o.z += __shfl_xor_sync(FULL, o.z, off);
            o.w += __shfl_xor_sync(FULL, o.w, off);
        }
        if (sub == 0) {
            float4 ci = __ldg((const float4*)(cur_item + (long long)tileB_id * DD) + quad);
            ((float4*)(out + (long long)tileB_id * DD))[quad] =
                make_float4(o.x + ci.x, o.y + ci.y, o.z + ci.z, o.w + ci.w);
        }
    }
}

extern "C" void kernel_launch(void* const* d_in, const int* in_sizes, int n_in,
                              void* d_out, int out_size) {
    // Select inputs by element count (robust to ordering):
    const float* cur_user = nullptr;
    const float* sim_user = nullptr;
    const float* cur_item = nullptr;
    const int*   mask     = nullptr;
    for (int i = 0; i < n_in; i++) {
        switch (in_sizes[i]) {
            case 16384:     cur_user = (const float*)d_in[i]; break;
            case 163840000: sim_user = (const float*)d_in[i]; break;
            case 3276800:   cur_item = (const float*)d_in[i]; break;
            case 5120000:   mask     = (const int*)d_in[i];   break;
        }
    }
    float* out = (float*)d_out;

    // 4 warps/block, 2 tiles/warp: grid (SS/2/4, BB) = (25, 512)
    dim3 grid(SS / 8, BB);
    DIB_attn_kernel<<<grid, 128>>>(cur_user, sim_user, cur_item, mask, out);
}

// round 17
// speedup vs baseline: 1.2947x; 1.2947x over previous
#include <cuda_runtime.h>
#include <math_constants.h>

#define BB 512
#define SS 200
#define UU 50
#define DD 32
#define NITER 13          // ceil(50 rows / 4 rows-per-iter)
#define NEG_INF_V (-1e9f)

__global__ __launch_bounds__(128)
void DIB_attn_kernel(const float* __restrict__ cur_user,   // [B, D]
                     const float* __restrict__ sim_user,   // [B, S, U, D]
                     const float* __restrict__ cur_item,   // [B, S, D]
                     const int* __restrict__ mask,          // [B, S, U] (bool -> int32)
                     float* __restrict__ out)               // [B, S, D]
{
    const unsigned FULL = 0xffffffffu;
    int gwarp = (blockIdx.x * blockDim.x + threadIdx.x) >> 5;   // one warp per (b,s)
    if (gwarp >= BB * SS) return;
    int lane = threadIdx.x & 31;
    int sub  = lane >> 3;       // 0..3 : row within 4-row group
    int quad = lane & 7;        // 0..7 : dims quad*4 .. quad*4+3

    int b = gwarp / SS;

    // ---- Mask first: 2 coalesced loads + 2 ballots -> 50-bit "unmasked" bitmap.
    const int* mrow = mask + (long long)gwarp * UU;
    int m0 = __ldg(mrow + lane);                        // u = 0..31
    unsigned bits0 = __ballot_sync(FULL, m0 == 0);
    int u2 = 32 + lane;
    int m1 = (u2 < UU) ? __ldg(mrow + u2) : 1;          // u = 32..49
    unsigned bits1 = __ballot_sync(FULL, (u2 < UU) && (m1 == 0));
    bool degen = (bits0 | bits1) == 0u;                 // all masked -> uniform

    float4 cu = __ldg((const float4*)(cur_user + b * DD) + quad);
    const float* tile = sim_user + (long long)gwarp * (UU * DD);

    // ---- Predicated tile load: masked rows make NO memory request (their
    //      128B line = 4 sectors is never fetched). Addresses identical to the
    //      full stream; no compaction, no gather.
    float4 v[NITER];
    #pragma unroll
    for (int i = 0; i < NITER; i++) {
        int u = i * 4 + sub;
        bool inb = (u < UU);
        bool un  = inb && (((u < 32 ? (bits0 >> u) : (bits1 >> (u - 32))) & 1u) != 0u);
        float4 vv = make_float4(0.f, 0.f, 0.f, 0.f);
        if (inb && (un || degen))
            vv = __ldg((const float4*)(tile + u * DD) + quad);
        v[i] = vv;
    }

    // ---- Dot products + scores (masked -> -1e9, pad -> -inf) ----
    float sc[NITER];
    #pragma unroll
    for (int i = 0; i < NITER; i++) {
        int u = i * 4 + sub;
        float p = v[i].x * cu.x + v[i].y * cu.y + v[i].z * cu.z + v[i].w * cu.w;
        p += __shfl_xor_sync(FULL, p, 1);
        p += __shfl_xor_sync(FULL, p, 2);
        p += __shfl_xor_sync(FULL, p, 4);               // 8-lane group holds score[u]
        bool inb = (u < UU);
        bool un  = inb && (((u < 32 ? (bits0 >> u) : (bits1 >> (u - 32))) & 1u) != 0u);
        sc[i] = inb ? (un ? p : NEG_INF_V) : -CUDART_INF_F;
    }

    // ---- Softmax over all 50 (masked rows get weight exactly 0; degen case:
    //      all sc=-1e9 -> uniform 1/50 over fully-loaded tile, matching ref) ----
    float mx = sc[0];
    #pragma unroll
    for (int i = 1; i < NITER; i++) mx = fmaxf(mx, sc[i]);
    mx = fmaxf(mx, __shfl_xor_sync(FULL, mx, 8));
    mx = fmaxf(mx, __shfl_xor_sync(FULL, mx, 16));

    float e[NITER];
    float s = 0.f;
    #pragma unroll
    for (int i = 0; i < NITER; i++) { e[i] = __expf(sc[i] - mx); s += e[i]; }
    s += __shfl_xor_sync(FULL, s, 8);
    s += __shfl_xor_sync(FULL, s, 16);
    float inv = __frcp_rn(s);

    // ---- Weighted sum (weights lane-local; v=0 for skipped rows anyway) ----
    float4 o = make_float4(0.f, 0.f, 0.f, 0.f);
    #pragma unroll
    for (int i = 0; i < NITER; i++) {
        float a = e[i] * inv;
        o.x = fmaf(a, v[i].x, o.x);
        o.y = fmaf(a, v[i].y, o.y);
        o.z = fmaf(a, v[i].z, o.z);
        o.w = fmaf(a, v[i].w, o.w);
    }

    // Reduce partial outputs across the 4 sub groups (same dims, different rows).
    #pragma unroll
    for (int off = 8; off <= 16; off <<= 1) {
        o.x += __shfl_xor_sync(FULL, o.x, off);
        o.y += __shfl_xor_sync(FULL, o.y, off);
        o.z += __shfl_xor_sync(FULL, o.z, off);
        o.w += __shfl_xor_sync(FULL, o.w, off);
    }

    // sub==0 lanes (8 of them) write the 128B output row.
    if (sub == 0) {
        float4 ci = __ldg((const float4*)(cur_item + (long long)gwarp * DD) + quad);
        float4 r = make_float4(o.x + ci.x, o.y + ci.y, o.z + ci.z, o.w + ci.w);
        ((float4*)(out + (long long)gwarp * DD))[quad] = r;
    }
}

extern "C" void kernel_launch(void* const* d_in, const int* in_sizes, int n_in,
                              void* d_out, int out_size) {
    // Select inputs by element count (robust to ordering):
    const float* cur_user = nullptr;
    const float* sim_user = nullptr;
    const float* cur_item = nullptr;
    const int*   mask     = nullptr;
    for (int i = 0; i < n_in; i++) {
        switch (in_sizes[i]) {
            case 16384:     cur_user = (const float*)d_in[i]; break;
            case 163840000: sim_user = (const float*)d_in[i]; break;
            case 3276800:   cur_item = (const float*)d_in[i]; break;
            case 5120000:   mask     = (const int*)d_in[i];   break;
        }
    }
    float* out = (float*)d_out;

    // 128-thread blocks: same compiled kernel as the 94.9us champion, finer
    // occupancy granularity at 80 regs (6 blocks x 4 warps = 24 warps/SM vs 21).
    int total_warps = BB * SS;              // 102400 (b,s) pairs, one warp each
    int threads = 128;
    int blocks = (total_warps * 32 + threads - 1) / threads;  // 25600
    DIB_attn_kernel<<<blocks, threads>>>(cur_user, sim_user, cur_item, mask, out);
}